// round 4
// baseline (speedup 1.0000x reference)
#include <cuda_runtime.h>
#include <cuda_bf16.h>

#define N_ATOMS 8192
#define NT 85
#define BINS 28
#define TILE 256
#define T_TILES (N_ATOMS / TILE)                 // 32
#define NBLOCKS (T_TILES * (T_TILES + 1) / 2)    // 528
#define THREADS 256
#define LUT_SIZE (NT * NT * BINS)                // 202300
#define LUT_BLOCKS ((LUT_SIZE + 255) / 256)      // 791

// Fused (e0, e1) LUT, symmetric in (t1,t2); indexed canonically (tlo,thi).
__device__ float2 g_lut[LUT_SIZE];
// Atoms bucket-sorted by type, packed as (x, y, z, res<<7|type).
__device__ float4 g_atoms[N_ATOMS];
__device__ double   g_sum;
__device__ unsigned g_count;

// One kernel does everything preparatory:
//   blocks [0, LUT_BLOCKS): build fused LUT, block 0 thread 0 zeros accumulators
//   block LUT_BLOCKS:       single-block 85-bucket type sort of the atoms
__global__ void prep_kernel(const float* __restrict__ pot,
                            const float* __restrict__ coords,
                            const int*  __restrict__ res_ids,
                            const int*  __restrict__ type_indices) {
    __shared__ int s_cursor[NT];

    if (blockIdx.x < LUT_BLOCKS) {
        int idx = blockIdx.x * 256 + threadIdx.x;
        if (idx == 0) { g_sum = 0.0; g_count = 0u; }
        if (idx < LUT_SIZE) {
            int d = idx % BINS;
            float e0 = pot[idx];
            float e1 = pot[(d == BINS - 1) ? idx : (idx + 1)];
            g_lut[idx] = make_float2(e0, e1);
        }
        return;
    }

    // ---- bucket sort by type (order within bucket irrelevant: sum is
    // invariant under atom permutation) ----
    int tid = threadIdx.x;
    for (int t = tid; t < NT; t += 256) s_cursor[t] = 0;
    __syncthreads();
    for (int i = tid; i < N_ATOMS; i += 256)
        atomicAdd(&s_cursor[type_indices[i]], 1);
    __syncthreads();
    if (tid == 0) {
        int run = 0;
        for (int t = 0; t < NT; ++t) { int c = s_cursor[t]; s_cursor[t] = run; run += c; }
    }
    __syncthreads();
    for (int i = tid; i < N_ATOMS; i += 256) {
        int t   = type_indices[i];
        int pos = atomicAdd(&s_cursor[t], 1);
        int packed = (res_ids[i] << 7) | t;     // res < 512, type < 128
        g_atoms[pos] = make_float4(coords[3 * i + 0],
                                   coords[3 * i + 1],
                                   coords[3 * i + 2],
                                   __int_as_float(packed));
    }
}

template <bool DIAG>
__device__ __forceinline__ float tile_sum(const float4* __restrict__ s_i,
                                          float4 aj, int jl, int jres, int jtype) {
    const float2* __restrict__ lut = g_lut;
    float acc = 0.0f;
#pragma unroll 8
    for (int il = 0; il < TILE; ++il) {
        float4 ai = s_i[il];                    // warp-uniform smem broadcast
        float dx = ai.x - aj.x;
        float dy = ai.y - aj.y;
        float dz = ai.z - aj.z;
        float d2 = fmaf(dx, dx, fmaf(dy, dy, dz * dz));

        int  pi  = __float_as_int(ai.w);
        int  sep = abs((pi >> 7) - jres);
        bool ok  = (sep > 2) & (d2 < 384.16f);  // 19.6^2 cutoff
        if (DIAG) ok &= (il < jl);

        if (ok) {
            float d2s = fmaxf(d2, 1e-12f);
            float d   = d2s * rsqrtf(d2s);      // ~2^-22 rel err, single MUFU
            float ds  = d * (1.0f / 0.7f);
            float dsc = fminf(ds, 27.0f);
            int   d0  = (int)dsc;               // dsc >= 0 -> trunc == floor
            float alpha = ds - (float)d0;       // e.y==e.x at d0==27, alpha inert
            int   it  = pi & 127;
            int   tlo = min(it, jtype);
            int   thi = max(it, jtype);
            float2 e  = __ldg(&lut[(tlo * NT + thi) * BINS + d0]);
            acc += fmaf(alpha, e.y - e.x, e.x);
        }
    }
    return acc;
}

__global__ __launch_bounds__(THREADS)
void dfire_kernel(float* __restrict__ out) {
    __shared__ float4 s_i[TILE];
    __shared__ float4 s_j[TILE];
    __shared__ double s_warp[THREADS / 32];

    // Decode linear block index -> (ti, tj), ti <= tj (row-major upper tri).
    int b  = blockIdx.x;
    int ti = (int)(((float)(2 * T_TILES + 1)
              - sqrtf((float)((2 * T_TILES + 1) * (2 * T_TILES + 1) - 8 * b))) * 0.5f);
    ti = max(0, min(T_TILES - 1, ti));
    while (ti * T_TILES - ti * (ti - 1) / 2 > b) --ti;
    while ((ti + 1) * T_TILES - (ti + 1) * ti / 2 <= b) ++ti;
    int tj = ti + (b - (ti * T_TILES - ti * (ti - 1) / 2));

    int tid = threadIdx.x;
    s_i[tid] = g_atoms[ti * TILE + tid];        // coalesced LDG.128
    s_j[tid] = g_atoms[tj * TILE + tid];
    __syncthreads();

    float4 aj   = s_j[tid];
    int    pj   = __float_as_int(aj.w);
    int    jres = pj >> 7;
    int    jtyp = pj & 127;

    float acc = (ti == tj) ? tile_sum<true >(s_i, aj, tid, jres, jtyp)
                           : tile_sum<false>(s_i, aj, tid, jres, jtyp);

    // warp shuffle reduce -> per-warp double -> block double -> global atomic
#pragma unroll
    for (int off = 16; off > 0; off >>= 1)
        acc += __shfl_xor_sync(0xFFFFFFFFu, acc, off);
    if ((tid & 31) == 0) s_warp[tid >> 5] = (double)acc;
    __syncthreads();

    if (tid == 0) {
        double s = 0.0;
#pragma unroll
        for (int w = 0; w < THREADS / 32; ++w) s += s_warp[w];
        atomicAdd(&g_sum, s);
        __threadfence();
        unsigned done = atomicAdd(&g_count, 1u);
        if (done == NBLOCKS - 1) {              // last block finalizes
            out[0] = (float)atomicAdd(&g_sum, 0.0);
        }
    }
}

extern "C" void kernel_launch(void* const* d_in, const int* in_sizes, int n_in,
                              void* d_out, int out_size) {
    // Input order: coords, pot_tensor, res_ids, type_indices, i_idx, j_idx
    const float* coords       = (const float*)d_in[0];
    const float* pot_tensor   = (const float*)d_in[1];
    const int*   res_ids      = (const int*)d_in[2];
    const int*   type_indices = (const int*)d_in[3];
    // i_idx / j_idx are deterministic triu indices, regenerated by the tile
    // decomposition; never read.
    (void)in_sizes; (void)n_in; (void)out_size;
    float* out = (float*)d_out;

    prep_kernel<<<LUT_BLOCKS + 1, 256>>>(pot_tensor, coords, res_ids, type_indices);
    dfire_kernel<<<NBLOCKS, THREADS>>>(out);
}

// round 5
// speedup vs baseline: 1.1856x; 1.1856x over previous
#include <cuda_runtime.h>
#include <cuda_bf16.h>

#define N_ATOMS 8192
#define NT 85
#define BINS 28
#define ROWSZ (NT * BINS)                        // 2380, type -> LUT row stride
#define TILE 128
#define T_TILES (N_ATOMS / TILE)                 // 64
#define NBLOCKS (T_TILES * (T_TILES + 1) / 2)    // 2080
#define THREADS 128
#define LUT_SIZE (NT * NT * BINS)                // 202300
#define LUT_BLOCKS ((LUT_SIZE + 511) / 512)      // 396
#define NSLOTS 32

// Fused (e0, e1) LUT (symmetric in types; direct [t1][t2] indexing is valid).
__device__ float2 g_lut[LUT_SIZE];
// Atoms bucket-sorted by type, packed as (x, y, z, res<<18 | type*2380).
__device__ float4 g_atoms[N_ATOMS];
__device__ double   g_sums[NSLOTS];
__device__ unsigned g_count;

// Prep: blocks [0, LUT_BLOCKS) build the fused LUT (+ block 0 zeros accums);
// block LUT_BLOCKS does a single-block 85-bucket type sort of the atoms
// (pair sum is invariant under atom permutation).
__global__ void prep_kernel(const float* __restrict__ pot,
                            const float* __restrict__ coords,
                            const int*  __restrict__ res_ids,
                            const int*  __restrict__ type_indices) {
    __shared__ int s_cursor[NT];

    if (blockIdx.x < LUT_BLOCKS) {
        int idx = blockIdx.x * 512 + threadIdx.x;
        if (blockIdx.x == 0 && threadIdx.x < NSLOTS + 1) {
            if (threadIdx.x < NSLOTS) g_sums[threadIdx.x] = 0.0;
            else g_count = 0u;
        }
        if (idx < LUT_SIZE) {
            int d = idx % BINS;
            float e0 = pot[idx];
            float e1 = pot[(d == BINS - 1) ? idx : (idx + 1)];
            g_lut[idx] = make_float2(e0, e1);
        }
        return;
    }

    int tid = threadIdx.x;
    for (int t = tid; t < NT; t += 512) s_cursor[t] = 0;
    __syncthreads();
    for (int i = tid; i < N_ATOMS; i += 512)
        atomicAdd(&s_cursor[type_indices[i]], 1);
    __syncthreads();
    if (tid == 0) {
        int run = 0;
        for (int t = 0; t < NT; ++t) { int c = s_cursor[t]; s_cursor[t] = run; run += c; }
    }
    __syncthreads();
    for (int i = tid; i < N_ATOMS; i += 512) {
        int t   = type_indices[i];
        int pos = atomicAdd(&s_cursor[t], 1);
        int packed = (res_ids[i] << 18) | (t * ROWSZ);   // res<512 (9b), t*2380<2^18
        g_atoms[pos] = make_float4(coords[3 * i + 0],
                                   coords[3 * i + 1],
                                   coords[3 * i + 2],
                                   __int_as_float(packed));
    }
}

template <bool DIAG>
__device__ __forceinline__ float tile_sum(const float4* __restrict__ s_i,
                                          float jx, float jy, float jz,
                                          int loB, int hiB, int jrow28, int jl) {
    const float2* __restrict__ lut = g_lut;
    float acc = 0.0f;
#pragma unroll 8
    for (int il = 0; il < TILE; ++il) {
        float4 ai = s_i[il];                       // warp-uniform smem broadcast
        float dx = ai.x - jx;
        float dy = ai.y - jy;
        float dz = ai.z - jz;
        float d2 = fmaf(dx, dx, fmaf(dy, dy, dz * dz));
        d2 = fmaxf(d2, 1e-12f);                    // guard rsqrt(0) -> NaN

        int   pi  = __float_as_int(ai.w);
        float rs  = rsqrtf(d2);
        float ds  = (d2 * rs) * (1.0f / 0.7f);     // d / 0.7
        float dsc = fminf(ds, 27.0f);
        int   d0  = (int)dsc;                      // >=0 -> trunc == floor
        float alpha = ds - (float)d0;              // inert at d0==27 (e1==e0)

        int base = (pi & 0x3FFFF) + jrow28 + d0;   // itype*2380 + jtype*28 + d0
        float2 e = __ldg(&lut[base]);              // always valid, always loaded

        // sep>2 in packed domain: ires>=jres+3 <=> pi>=hiB; ires<=jres-3 <=> pi<loB
        bool ok = (pi >= hiB) | (pi < loB);
        ok &= (d2 < 384.16f);                      // 19.6^2
        if (DIAG) ok &= (il < jl);

        float val = fmaf(alpha, e.y - e.x, e.x);
        if (ok) acc += val;                        // predicated FADD
    }
    return acc;
}

__global__ __launch_bounds__(THREADS, 12)
void dfire_kernel(float* __restrict__ out) {
    __shared__ float4 s_i[TILE];
    __shared__ double s_warp[THREADS / 32];

    // Linear block -> (ti, tj), ti <= tj, row-major upper triangle of 64x64.
    int b  = blockIdx.x;
    int ti = (int)(((float)(2 * T_TILES + 1)
              - sqrtf((float)((2 * T_TILES + 1) * (2 * T_TILES + 1) - 8 * b))) * 0.5f);
    ti = max(0, min(T_TILES - 1, ti));
    while (ti * T_TILES - ti * (ti - 1) / 2 > b) --ti;
    while ((ti + 1) * T_TILES - (ti + 1) * ti / 2 <= b) ++ti;
    int tj = ti + (b - (ti * T_TILES - ti * (ti - 1) / 2));

    int tid = threadIdx.x;
    s_i[tid] = g_atoms[ti * TILE + tid];           // coalesced LDG.128 -> STS
    float4 aj = g_atoms[tj * TILE + tid];          // this thread's j atom
    __syncthreads();

    int pj     = __float_as_int(aj.w);
    int jres   = pj >> 18;
    int jtype  = (pj & 0x3FFFF) / ROWSZ;           // one div per thread (setup)
    int jrow28 = jtype * BINS;
    int loB    = (jres - 2) << 18;                 // pi <  loB  <=> ires <= jres-3
    int hiB    = (jres + 3) << 18;                 // pi >= hiB  <=> ires >= jres+3

    float acc = (ti == tj)
        ? tile_sum<true >(s_i, aj.x, aj.y, aj.z, loB, hiB, jrow28, tid)
        : tile_sum<false>(s_i, aj.x, aj.y, aj.z, loB, hiB, jrow28, tid);

#pragma unroll
    for (int off = 16; off > 0; off >>= 1)
        acc += __shfl_xor_sync(0xFFFFFFFFu, acc, off);
    if ((tid & 31) == 0) s_warp[tid >> 5] = (double)acc;
    __syncthreads();

    if (tid == 0) {
        double s = s_warp[0] + s_warp[1] + s_warp[2] + s_warp[3];
        atomicAdd(&g_sums[b & (NSLOTS - 1)], s);   // 32 slots: no hot-address serialize
        __threadfence();
        unsigned done = atomicAdd(&g_count, 1u);
        if (done == NBLOCKS - 1) {                 // last block finalizes
            double tot = 0.0;
#pragma unroll
            for (int k = 0; k < NSLOTS; ++k)
                tot += atomicAdd(&g_sums[k], 0.0); // forced coherent read
            out[0] = (float)tot;
        }
    }
}

extern "C" void kernel_launch(void* const* d_in, const int* in_sizes, int n_in,
                              void* d_out, int out_size) {
    // Input order: coords, pot_tensor, res_ids, type_indices, i_idx, j_idx
    const float* coords       = (const float*)d_in[0];
    const float* pot_tensor   = (const float*)d_in[1];
    const int*   res_ids      = (const int*)d_in[2];
    const int*   type_indices = (const int*)d_in[3];
    // i_idx / j_idx are deterministic triu indices, regenerated by the tile
    // decomposition; never read.
    (void)in_sizes; (void)n_in; (void)out_size;
    float* out = (float*)d_out;

    prep_kernel<<<LUT_BLOCKS + 1, 512>>>(pot_tensor, coords, res_ids, type_indices);
    dfire_kernel<<<NBLOCKS, THREADS>>>(out);
}

// round 6
// speedup vs baseline: 1.2601x; 1.0628x over previous
#include <cuda_runtime.h>
#include <cuda_bf16.h>

#define N_ATOMS 8192
#define NT 85
#define BINS 28
#define ROWSZ (NT * BINS)                        // 2380
#define TILE 128
#define T_TILES (N_ATOMS / TILE)                 // 64
#define NBLOCKS (T_TILES * (T_TILES + 1) / 2)    // 2080
#define GRID_PERSIST 1776                        // 148 SMs x 12 blocks
#define THREADS 128
#define LUT_SIZE (NT * NT * BINS)                // 202300
#define LUT_BLOCKS ((LUT_SIZE + 511) / 512)      // 396
#define NSLOTS 32
#define INV07 1.42857142857142857f               // 1/0.7

// Slope-intercept LUT: (A, B) with e(ds) = A + B*ds on bin d0 = floor(ds).
__device__ float2 g_lut[LUT_SIZE];
// Atoms bucket-sorted by type; coords pre-scaled by 1/0.7;
// w packs res<<18 | type*2380.
__device__ float4 g_atoms[N_ATOMS];
__device__ double   g_sums[NSLOTS];
__device__ unsigned g_count;

__global__ void prep_kernel(const float* __restrict__ pot,
                            const float* __restrict__ coords,
                            const int*  __restrict__ res_ids,
                            const int*  __restrict__ type_indices) {
    __shared__ int s_cursor[NT];

    if (blockIdx.x < LUT_BLOCKS) {
        int idx = blockIdx.x * 512 + threadIdx.x;
        if (blockIdx.x == 0 && threadIdx.x <= NSLOTS) {
            if (threadIdx.x < NSLOTS) g_sums[threadIdx.x] = 0.0;
            else g_count = 0u;
        }
        if (idx < LUT_SIZE) {
            int   d  = idx % BINS;
            float e0 = pot[idx];
            float e1 = (d == BINS - 1) ? e0 : pot[idx + 1];
            float B  = e1 - e0;
            float A  = fmaf(-(float)d, B, e0);   // e = A + B*ds on [d, d+1)
            g_lut[idx] = make_float2(A, B);
        }
        return;
    }

    // Single-block 85-bucket type sort (sum is permutation-invariant).
    int tid = threadIdx.x;
    for (int t = tid; t < NT; t += 512) s_cursor[t] = 0;
    __syncthreads();
    for (int i = tid; i < N_ATOMS; i += 512)
        atomicAdd(&s_cursor[type_indices[i]], 1);
    __syncthreads();
    if (tid == 0) {
        int run = 0;
        for (int t = 0; t < NT; ++t) { int c = s_cursor[t]; s_cursor[t] = run; run += c; }
    }
    __syncthreads();
    for (int i = tid; i < N_ATOMS; i += 512) {
        int t   = type_indices[i];
        int pos = atomicAdd(&s_cursor[t], 1);
        int packed = (res_ids[i] << 18) | (t * ROWSZ);
        g_atoms[pos] = make_float4(coords[3 * i + 0] * INV07,
                                   coords[3 * i + 1] * INV07,
                                   coords[3 * i + 2] * INV07,
                                   __int_as_float(packed));
    }
}

template <bool DIAG>
__device__ __forceinline__ float tile_sum(const float4* __restrict__ s_i,
                                          float jx, float jy, float jz,
                                          int loB, int hiB,
                                          const float2* __restrict__ jlut, int jl) {
    float acc = 0.0f;
#pragma unroll 8
    for (int il = 0; il < TILE; ++il) {
        float4 ai = s_i[il];                     // warp-uniform smem broadcast
        float dx = ai.x - jx;
        float dy = ai.y - jy;
        float dz = ai.z - jz;
        float d2 = fmaf(dx, dx, fmaf(dy, dy, dz * dz));  // = (d/0.7)^2

        int   pi  = __float_as_int(ai.w);
        float ds  = d2 * rsqrtf(d2);             // d/0.7; NaN only at il==jl (DIAG, predicated out)
        float dsc = fminf(ds, 27.0f);            // fminf(NaN,27)=27 -> index stays valid
        int   d0  = (int)dsc;

        float2 e = __ldg(&jlut[(pi & 0x3FFFF) + d0]);  // A,B; always valid

        bool ok = (pi >= hiB) | (pi < loB);      // sep > 2 in packed domain
        ok &= (d2 < 784.0f);                     // 28^2  <=>  d < 19.6
        if (DIAG) ok &= (il < jl);

        float val = fmaf(e.y, ds, e.x);          // A + B*ds
        if (ok) acc += val;                      // predicated FADD
    }
    return acc;
}

__global__ __launch_bounds__(THREADS, 12)
void dfire_kernel(float* __restrict__ out) {
    __shared__ float4 s_i[TILE];
    __shared__ double s_warp[THREADS / 32];

    const int tid = threadIdx.x;
    double block_sum = 0.0;                      // thread 0's copy is authoritative

    for (int b = blockIdx.x; b < NBLOCKS; b += GRID_PERSIST) {
        // Linear b -> (ti, tj), ti <= tj, row-major upper triangle of 64x64.
        int ti = (int)(((float)(2 * T_TILES + 1)
                  - sqrtf((float)((2 * T_TILES + 1) * (2 * T_TILES + 1) - 8 * b))) * 0.5f);
        ti = max(0, min(T_TILES - 1, ti));
        while (ti * T_TILES - ti * (ti - 1) / 2 > b) --ti;
        while ((ti + 1) * T_TILES - (ti + 1) * ti / 2 <= b) ++ti;
        int tj = ti + (b - (ti * T_TILES - ti * (ti - 1) / 2));

        __syncthreads();                         // s_i / s_warp reuse across tiles
        s_i[tid] = g_atoms[ti * TILE + tid];
        float4 aj = g_atoms[tj * TILE + tid];
        __syncthreads();

        int pj     = __float_as_int(aj.w);
        int jres   = pj >> 18;
        int jtype  = (pj & 0x3FFFF) / ROWSZ;     // once per tile
        int loB    = (jres - 2) << 18;           // pi <  loB  <=> ires <= jres-3
        int hiB    = (jres + 3) << 18;           // pi >= hiB  <=> ires >= jres+3
        const float2* jlut = g_lut + jtype * BINS;

        float acc = (ti == tj)
            ? tile_sum<true >(s_i, aj.x, aj.y, aj.z, loB, hiB, jlut, tid)
            : tile_sum<false>(s_i, aj.x, aj.y, aj.z, loB, hiB, jlut, tid);

#pragma unroll
        for (int off = 16; off > 0; off >>= 1)
            acc += __shfl_xor_sync(0xFFFFFFFFu, acc, off);
        if ((tid & 31) == 0) s_warp[tid >> 5] = (double)acc;
        __syncthreads();
        if (tid == 0)
            block_sum += s_warp[0] + s_warp[1] + s_warp[2] + s_warp[3];
    }

    if (tid == 0) {
        atomicAdd(&g_sums[blockIdx.x & (NSLOTS - 1)], block_sum);
        __threadfence();
        unsigned done = atomicAdd(&g_count, 1u);
        if (done == GRID_PERSIST - 1) {          // last block finalizes
            double tot = 0.0;
#pragma unroll
            for (int k = 0; k < NSLOTS; ++k)
                tot += atomicAdd(&g_sums[k], 0.0);
            out[0] = (float)tot;
        }
    }
}

extern "C" void kernel_launch(void* const* d_in, const int* in_sizes, int n_in,
                              void* d_out, int out_size) {
    // Input order: coords, pot_tensor, res_ids, type_indices, i_idx, j_idx
    const float* coords       = (const float*)d_in[0];
    const float* pot_tensor   = (const float*)d_in[1];
    const int*   res_ids      = (const int*)d_in[2];
    const int*   type_indices = (const int*)d_in[3];
    // i_idx / j_idx are the deterministic triu indices, regenerated implicitly
    // by the tile decomposition; never read.
    (void)in_sizes; (void)n_in; (void)out_size;
    float* out = (float*)d_out;

    prep_kernel<<<LUT_BLOCKS + 1, 512>>>(pot_tensor, coords, res_ids, type_indices);
    dfire_kernel<<<GRID_PERSIST, THREADS>>>(out);
}

// round 8
// speedup vs baseline: 1.2676x; 1.0060x over previous
#include <cuda_runtime.h>
#include <cuda_bf16.h>

#define N_ATOMS 8192
#define NT 85
#define BINS 28
#define BINS2 29                                  // 28 real bins + zero pad bin
#define ROWSZ2 (NT * BINS2)                       // 2465: itype -> LUT row offset
#define TILE 128
#define T_TILES (N_ATOMS / TILE)                  // 64
#define NBLOCKS (T_TILES * (T_TILES + 1) / 2)     // 2080 tiles
#define NUNITS (NBLOCKS * 4)                      // 8320 quarter-tile units
#define GRID_PERSIST 1776                         // 148 SMs x 12
#define THREADS 128
#define LUT_SIZE (NT * NT * BINS2)                // 209525
#define LUT_BLOCKS ((LUT_SIZE + 511) / 512)       // 410
#define NSLOTS 32
#define INV07 1.42857142857142857f

// Slope-intercept LUT with zero pad: e(ds) = A + B*ds on bin d0 = floor(ds);
// bin 28 = (0,0) so pairs beyond the 19.6A cutoff contribute exactly 0.
__device__ float2 g_lut[LUT_SIZE];
// Atoms bucket-sorted by type; coords pre-scaled by 1/0.7;
// w packs res<<18 | itype*ROWSZ2 (res<512 -> 9 bits; 84*2465 < 2^18).
__device__ float4 g_atoms[N_ATOMS];
__device__ int    g_tij[NBLOCKS];                 // tile b -> (ti<<8 | tj)
__device__ double   g_sums[NSLOTS];
__device__ unsigned g_count;

__global__ void prep_kernel(const float* __restrict__ pot,
                            const float* __restrict__ coords,
                            const int*  __restrict__ res_ids,
                            const int*  __restrict__ type_indices) {
    __shared__ int s_cursor[NT];

    if (blockIdx.x < LUT_BLOCKS) {
        int idx = blockIdx.x * 512 + threadIdx.x;
        if (blockIdx.x == 0 && threadIdx.x <= NSLOTS) {
            if (threadIdx.x < NSLOTS) g_sums[threadIdx.x] = 0.0;
            else g_count = 0u;
        }
        if (idx < LUT_SIZE) {
            int t12 = idx / BINS2;
            int d   = idx - t12 * BINS2;
            float2 v;
            if (d >= BINS) {
                v = make_float2(0.0f, 0.0f);     // pad bin: beyond cutoff -> 0
            } else {
                float e0 = pot[t12 * BINS + d];
                float e1 = (d == BINS - 1) ? e0 : pot[t12 * BINS + d + 1];
                float B  = e1 - e0;
                v = make_float2(fmaf(-(float)d, B, e0), B);
            }
            g_lut[idx] = v;
        }
        // build tile decode table (ti <= tj, row-major upper triangle)
        int b = blockIdx.x * 512 + threadIdx.x;
        if (b < NBLOCKS) {
            int ti = 0, acc = 0;
            while (acc + (T_TILES - ti) <= b) { acc += T_TILES - ti; ++ti; }
            int tj = ti + (b - acc);
            g_tij[b] = (ti << 8) | tj;
        }
        return;
    }

    // Single-block 85-bucket type sort (pair sum is permutation-invariant).
    int tid = threadIdx.x;
    for (int t = tid; t < NT; t += 512) s_cursor[t] = 0;
    __syncthreads();
    for (int i = tid; i < N_ATOMS; i += 512)
        atomicAdd(&s_cursor[type_indices[i]], 1);
    __syncthreads();
    if (tid == 0) {
        int run = 0;
        for (int t = 0; t < NT; ++t) { int c = s_cursor[t]; s_cursor[t] = run; run += c; }
    }
    __syncthreads();
    for (int i = tid; i < N_ATOMS; i += 512) {
        int t   = type_indices[i];
        int pos = atomicAdd(&s_cursor[t], 1);
        int packed = (res_ids[i] << 18) | (t * ROWSZ2);
        g_atoms[pos] = make_float4(coords[3 * i + 0] * INV07,
                                   coords[3 * i + 1] * INV07,
                                   coords[3 * i + 2] * INV07,
                                   __int_as_float(packed));
    }
}

// 32-i-atom chunk vs this thread's j atom. i atoms via warp-uniform L1 loads.
template <bool DIAG>
__device__ __forceinline__ float chunk_sum(const float4* __restrict__ ibase,
                                           float jx, float jy, float jz,
                                           int loB, const float2* __restrict__ jlut,
                                           int lim) {
    float acc = 0.0f;
#pragma unroll 8
    for (int il = 0; il < 32; ++il) {
        float4 ai = __ldg(&ibase[il]);            // uniform addr, L1-resident
        float dx = ai.x - jx;
        float dy = ai.y - jy;
        float dz = ai.z - jz;
        float d2 = fmaf(dx, dx, fmaf(dy, dy, dz * dz));   // (d/0.7)^2
        d2 = fmaxf(d2, 1e-12f);                   // self-pair / dup-coord guard

        int   pi  = __float_as_int(ai.w);
        float ds  = d2 * rsqrtf(d2);              // d/0.7
        float dsc = fminf(ds, 28.0f);             // >=28 -> zero pad bin
        int   d0  = (int)dsc;

        float2 e = __ldg(&jlut[(pi & 0x3FFFF) + d0]);

        // sep>2: ires outside [jres-2, jres+2]  <=>  (u32)(pi - loB) >= 5<<18
        bool ok = (unsigned)(pi - loB) >= (5u << 18);
        if (DIAG) ok &= (il < lim);

        float val = fmaf(e.y, ds, e.x);           // A + B*ds (0 beyond cutoff)
        if (ok) acc += val;                       // predicated FADD
    }
    return acc;
}

__global__ __launch_bounds__(THREADS, 12)
void dfire_kernel(float* __restrict__ out) {
    __shared__ double s_warp[THREADS / 32];
    const int tid = threadIdx.x;

    float acc = 0.0f;                             // per-thread, across all units

    for (int u = blockIdx.x; u < NUNITS; u += GRID_PERSIST) {
        int b  = u >> 2;
        int q  = u & 3;
        int tt = g_tij[b];                        // 1 LDG decode
        int ti = tt >> 8;
        int tj = tt & 255;

        const float4* ibase = g_atoms + ti * TILE + q * 32;
        float4 aj = g_atoms[tj * TILE + tid];     // coalesced LDG.128

        int pj    = __float_as_int(aj.w);
        int jres  = pj >> 18;
        int jtype = (pj & 0x3FFFF) / ROWSZ2;      // const-div: mulhi+shift
        int loB   = (jres - 2) << 18;
        const float2* jlut = g_lut + jtype * BINS2;

        if (ti == tj) {
            int lim = tid - q * 32;               // i_local < j_local
            acc += chunk_sum<true >(ibase, aj.x, aj.y, aj.z, loB, jlut, lim);
        } else {
            acc += chunk_sum<false>(ibase, aj.x, aj.y, aj.z, loB, jlut, 0);
        }
    }

#pragma unroll
    for (int off = 16; off > 0; off >>= 1)
        acc += __shfl_xor_sync(0xFFFFFFFFu, acc, off);
    if ((tid & 31) == 0) s_warp[tid >> 5] = (double)acc;
    __syncthreads();

    if (tid == 0) {
        double s = s_warp[0] + s_warp[1] + s_warp[2] + s_warp[3];
        atomicAdd(&g_sums[blockIdx.x & (NSLOTS - 1)], s);
        __threadfence();
        unsigned done = atomicAdd(&g_count, 1u);
        if (done == GRID_PERSIST - 1) {           // last block finalizes
            double tot = 0.0;
#pragma unroll
            for (int k = 0; k < NSLOTS; ++k)
                tot += atomicAdd(&g_sums[k], 0.0);
            out[0] = (float)tot;
        }
    }
}

extern "C" void kernel_launch(void* const* d_in, const int* in_sizes, int n_in,
                              void* d_out, int out_size) {
    // Input order: coords, pot_tensor, res_ids, type_indices, i_idx, j_idx
    const float* coords       = (const float*)d_in[0];
    const float* pot_tensor   = (const float*)d_in[1];
    const int*   res_ids      = (const int*)d_in[2];
    const int*   type_indices = (const int*)d_in[3];
    // i_idx / j_idx are the deterministic triu indices; regenerated implicitly.
    (void)in_sizes; (void)n_in; (void)out_size;
    float* out = (float*)d_out;

    prep_kernel<<<LUT_BLOCKS + 1, 512>>>(pot_tensor, coords, res_ids, type_indices);
    dfire_kernel<<<GRID_PERSIST, THREADS>>>(out);
}

// round 10
// speedup vs baseline: 1.2775x; 1.0078x over previous
#include <cuda_runtime.h>
#include <cuda_bf16.h>

#define N_ATOMS 8192
#define NT 85
#define BINS 28
#define BINS2 29                                  // 28 real bins + zero pad bin
#define ROWSZ2 (NT * BINS2)                       // 2465
#define TILE 128
#define T_TILES (N_ATOMS / TILE)                  // 64
#define NTILEPAIRS (T_TILES * (T_TILES + 1) / 2)  // 2080
#define NUNITS (NTILEPAIRS * 4)                   // 8320 quarter-tile units
#define BLOCKS_PER_SM 10
#define GRID_PERSIST (148 * BLOCKS_PER_SM)        // 1480
#define THREADS 128
#define LUT_SIZE (NT * NT * BINS2)                // 209525
#define LUT_BLOCKS ((LUT_SIZE + 511) / 512)       // 410
#define NSLOTS 32
#define INV07 1.42857142857142857f

typedef unsigned long long u64;

#define F32X2_ADD(d, a, b) \
    asm("add.rn.f32x2 %0, %1, %2;" : "=l"(d) : "l"(a), "l"(b))
#define F32X2_MUL(d, a, b) \
    asm("mul.rn.f32x2 %0, %1, %2;" : "=l"(d) : "l"(a), "l"(b))
#define F32X2_FMA(d, a, b, c) \
    asm("fma.rn.f32x2 %0, %1, %2, %3;" : "=l"(d) : "l"(a), "l"(b), "l"(c))

__device__ __forceinline__ u64 pack2(float lo, float hi) {
    return __double_as_longlong(
        __hiloint2double(__float_as_int(hi), __float_as_int(lo)));
}
__device__ __forceinline__ float lo_f(u64 v) {
    return __int_as_float(__double2loint(__longlong_as_double(v)));
}
__device__ __forceinline__ float hi_f(u64 v) {
    return __int_as_float(__double2hiint(__longlong_as_double(v)));
}
__device__ __forceinline__ int lo_i(u64 v) {
    return __double2loint(__longlong_as_double(v));
}
__device__ __forceinline__ int hi_i(u64 v) {
    return __double2hiint(__longlong_as_double(v));
}

// Slope-intercept LUT with zero pad bin 28 (beyond 19.6A cutoff -> exactly 0).
__device__ float2 g_lut[LUT_SIZE];
// Atoms bucket-sorted by type, coords pre-scaled by 1/0.7; j-side AoS view.
__device__ float4 g_atoms[N_ATOMS];
// i-side pair-packed view: per i-pair two double2: (x0x1,y0y1),(z0z1,w0w1).
__device__ double2 g_ipairs[N_ATOMS];             // 2 double2 per atom pair
__device__ int    g_tij[NTILEPAIRS];              // tile b -> (ti<<8 | tj)
__device__ double   g_sums[NSLOTS];
__device__ unsigned g_count;

__global__ void prep_kernel(const float* __restrict__ pot,
                            const float* __restrict__ coords,
                            const int*  __restrict__ res_ids,
                            const int*  __restrict__ type_indices) {
    __shared__ int s_cursor[NT];

    if (blockIdx.x < LUT_BLOCKS) {
        int idx = blockIdx.x * 512 + threadIdx.x;
        if (blockIdx.x == 0 && threadIdx.x <= NSLOTS) {
            if (threadIdx.x < NSLOTS) g_sums[threadIdx.x] = 0.0;
            else g_count = 0u;
        }
        if (idx < LUT_SIZE) {
            int t12 = idx / BINS2;
            int d   = idx - t12 * BINS2;
            float2 v;
            if (d >= BINS) {
                v = make_float2(0.0f, 0.0f);      // pad bin
            } else {
                float e0 = pot[t12 * BINS + d];
                float e1 = (d == BINS - 1) ? e0 : pot[t12 * BINS + d + 1];
                float B  = e1 - e0;
                v = make_float2(fmaf(-(float)d, B, e0), B);
            }
            g_lut[idx] = v;
        }
        int b = blockIdx.x * 512 + threadIdx.x;   // tile decode table
        if (b < NTILEPAIRS) {
            int ti = 0, acc = 0;
            while (acc + (T_TILES - ti) <= b) { acc += T_TILES - ti; ++ti; }
            g_tij[b] = (ti << 8) | (ti + (b - acc));
        }
        return;
    }

    // Single-block 85-bucket type sort (pair sum is permutation-invariant).
    int tid = threadIdx.x;
    for (int t = tid; t < NT; t += 512) s_cursor[t] = 0;
    __syncthreads();
    for (int i = tid; i < N_ATOMS; i += 512)
        atomicAdd(&s_cursor[type_indices[i]], 1);
    __syncthreads();
    if (tid == 0) {
        int run = 0;
        for (int t = 0; t < NT; ++t) { int c = s_cursor[t]; s_cursor[t] = run; run += c; }
    }
    __syncthreads();
    for (int i = tid; i < N_ATOMS; i += 512) {
        int t   = type_indices[i];
        int pos = atomicAdd(&s_cursor[t], 1);
        int packed = (res_ids[i] << 18) | (t * ROWSZ2);
        g_atoms[pos] = make_float4(coords[3 * i + 0] * INV07,
                                   coords[3 * i + 1] * INV07,
                                   coords[3 * i + 2] * INV07,
                                   __int_as_float(packed));
    }
    __syncthreads();                              // block-wide gmem visibility
    // Build the pair-packed i-side mirror.
    for (int p = tid; p < N_ATOMS / 2; p += 512) {
        float4 a0 = g_atoms[2 * p + 0];
        float4 a1 = g_atoms[2 * p + 1];
        double2 v0, v1;
        v0.x = __longlong_as_double(pack2(a0.x, a1.x));
        v0.y = __longlong_as_double(pack2(a0.y, a1.y));
        v1.x = __longlong_as_double(pack2(a0.z, a1.z));
        v1.y = __longlong_as_double(pack2(a0.w, a1.w));
        g_ipairs[2 * p + 0] = v0;
        g_ipairs[2 * p + 1] = v1;
    }
}

// 32 i atoms (16 packed pairs) vs this thread's j atom.
template <bool DIAG>
__device__ __forceinline__ float chunk_sum(const double2* __restrict__ ib,
                                           u64 jxn, u64 jyn, u64 jzn,
                                           int loB, const float2* __restrict__ jlut,
                                           int lim) {
    float acc0 = 0.0f, acc1 = 0.0f;
#pragma unroll
    for (int k = 0; k < 16; ++k) {
        double2 v0 = __ldg(&ib[2 * k + 0]);       // (x0x1, y0y1) uniform LDG.128
        double2 v1 = __ldg(&ib[2 * k + 1]);       // (z0z1, w0w1)
        u64 xs = __double_as_longlong(v0.x);
        u64 ys = __double_as_longlong(v0.y);
        u64 zs = __double_as_longlong(v1.x);
        u64 ws = __double_as_longlong(v1.y);

        u64 dx2, dy2, dz2, d2p;
        F32X2_ADD(dx2, xs, jxn);                  // (xi - xj) x2
        F32X2_ADD(dy2, ys, jyn);
        F32X2_ADD(dz2, zs, jzn);
        F32X2_MUL(d2p, dx2, dx2);
        F32X2_FMA(d2p, dy2, dy2, d2p);
        F32X2_FMA(d2p, dz2, dz2, d2p);            // (d/0.7)^2 for both pairs

        {   // pair 0 (i local = 2k)
            float d2 = fmaxf(lo_f(d2p), 1e-12f);
            int   pi = lo_i(ws);
            float ds = d2 * rsqrtf(d2);
            float dsc = fminf(ds, 28.0f);
            int   d0 = (int)dsc;
            float2 e = __ldg(&jlut[(pi & 0x3FFFF) + d0]);
            bool ok = (unsigned)(pi - loB) >= (5u << 18);   // sep > 2
            if (DIAG) ok &= (2 * k < lim);
            float val = fmaf(e.y, ds, e.x);
            if (ok) acc0 += val;
        }
        {   // pair 1 (i local = 2k+1)
            float d2 = fmaxf(hi_f(d2p), 1e-12f);
            int   pi = hi_i(ws);
            float ds = d2 * rsqrtf(d2);
            float dsc = fminf(ds, 28.0f);
            int   d0 = (int)dsc;
            float2 e = __ldg(&jlut[(pi & 0x3FFFF) + d0]);
            bool ok = (unsigned)(pi - loB) >= (5u << 18);
            if (DIAG) ok &= (2 * k + 1 < lim);
            float val = fmaf(e.y, ds, e.x);
            if (ok) acc1 += val;
        }
    }
    return acc0 + acc1;
}

__global__ __launch_bounds__(THREADS, BLOCKS_PER_SM)
void dfire_kernel(float* __restrict__ out) {
    __shared__ double s_warp[THREADS / 32];
    const int tid = threadIdx.x;

    float acc = 0.0f;

    for (int u = blockIdx.x; u < NUNITS; u += GRID_PERSIST) {
        int b  = u >> 2;
        int q  = u & 3;
        int tt = g_tij[b];
        int ti = tt >> 8;
        int tj = tt & 255;

        // i chunk: 32 atoms = 16 packed pairs = 32 double2's
        const double2* ib = g_ipairs + (ti * TILE + q * 32);
        float4 aj = g_atoms[tj * TILE + tid];     // coalesced LDG.128

        int pj    = __float_as_int(aj.w);
        int jres  = pj >> 18;
        int jtype = (pj & 0x3FFFF) / ROWSZ2;
        int loB   = (jres - 2) << 18;
        const float2* jlut = g_lut + jtype * BINS2;
        u64 jxn = pack2(-aj.x, -aj.x);
        u64 jyn = pack2(-aj.y, -aj.y);
        u64 jzn = pack2(-aj.z, -aj.z);

        if (ti == tj) {
            int lim = tid - q * 32;               // i_local < j_local
            acc += chunk_sum<true >(ib, jxn, jyn, jzn, loB, jlut, lim);
        } else {
            acc += chunk_sum<false>(ib, jxn, jyn, jzn, loB, jlut, 0);
        }
    }

#pragma unroll
    for (int off = 16; off > 0; off >>= 1)
        acc += __shfl_xor_sync(0xFFFFFFFFu, acc, off);
    if ((tid & 31) == 0) s_warp[tid >> 5] = (double)acc;
    __syncthreads();

    if (tid == 0) {
        double s = s_warp[0] + s_warp[1] + s_warp[2] + s_warp[3];
        atomicAdd(&g_sums[blockIdx.x & (NSLOTS - 1)], s);
        __threadfence();
        unsigned done = atomicAdd(&g_count, 1u);
        if (done == GRID_PERSIST - 1) {           // last block finalizes
            double tot = 0.0;
#pragma unroll
            for (int k = 0; k < NSLOTS; ++k)
                tot += atomicAdd(&g_sums[k], 0.0);
            out[0] = (float)tot;
        }
    }
}

extern "C" void kernel_launch(void* const* d_in, const int* in_sizes, int n_in,
                              void* d_out, int out_size) {
    // Input order: coords, pot_tensor, res_ids, type_indices, i_idx, j_idx
    const float* coords       = (const float*)d_in[0];
    const float* pot_tensor   = (const float*)d_in[1];
    const int*   res_ids      = (const int*)d_in[2];
    const int*   type_indices = (const int*)d_in[3];
    // i_idx / j_idx are the deterministic triu indices; regenerated implicitly.
    (void)in_sizes; (void)n_in; (void)out_size;
    float* out = (float*)d_out;

    prep_kernel<<<LUT_BLOCKS + 1, 512>>>(pot_tensor, coords, res_ids, type_indices);
    dfire_kernel<<<GRID_PERSIST, THREADS>>>(out);
}

// round 12
// speedup vs baseline: 1.3244x; 1.0367x over previous
#include <cuda_runtime.h>
#include <cuda_bf16.h>

#define N_ATOMS 8192
#define NT 85
#define BINS 28
#define BINS2 29                                  // 28 real bins + zero pad bin
#define ROWSZ2 (NT * BINS2)                       // 2465
#define TILE 128
#define T_TILES (N_ATOMS / TILE)                  // 64
#define NTILEPAIRS (T_TILES * (T_TILES + 1) / 2)  // 2080
#define NUNITS (NTILEPAIRS * 4)                   // 8320 quarter-tile units
#define BLOCKS_PER_SM 10
#define GRID_PERSIST (148 * BLOCKS_PER_SM)        // 1480
#define THREADS 128
#define LUT_SIZE (NT * NT * BINS2)                // 209525
#define LUT_BLOCKS ((LUT_SIZE + 511) / 512)       // 410
#define HIST_BLOCKS 16                            // 16 x 512 = 8192 atoms
#define NSLOTS 32
#define INV07 1.42857142857142857f

typedef unsigned long long u64;

#define F32X2_ADD(d, a, b) \
    asm("add.rn.f32x2 %0, %1, %2;" : "=l"(d) : "l"(a), "l"(b))
#define F32X2_MUL(d, a, b) \
    asm("mul.rn.f32x2 %0, %1, %2;" : "=l"(d) : "l"(a), "l"(b))
#define F32X2_FMA(d, a, b, c) \
    asm("fma.rn.f32x2 %0, %1, %2, %3;" : "=l"(d) : "l"(a), "l"(b), "l"(c))

__device__ __forceinline__ u64 pack2(float lo, float hi) {
    return __double_as_longlong(
        __hiloint2double(__float_as_int(hi), __float_as_int(lo)));
}
__device__ __forceinline__ float lo_f(u64 v) {
    return __int_as_float(__double2loint(__longlong_as_double(v)));
}
__device__ __forceinline__ float hi_f(u64 v) {
    return __int_as_float(__double2hiint(__longlong_as_double(v)));
}
__device__ __forceinline__ int lo_i(u64 v) {
    return __double2loint(__longlong_as_double(v));
}
__device__ __forceinline__ int hi_i(u64 v) {
    return __double2hiint(__longlong_as_double(v));
}

// Slope-intercept LUT with zero pad bin 28 (beyond 19.6A cutoff -> exactly 0).
__device__ float2 g_lut[LUT_SIZE];
// Atoms bucket-sorted by type, coords pre-scaled by 1/0.7; j-side AoS view.
__device__ float4 g_atoms[N_ATOMS];
// i-side pair-packed view: per atom pair 8 floats [x0,x1,y0,y1,z0,z1,w0,w1].
__device__ double2 g_ipairs[N_ATOMS];
__device__ int    g_tij[NTILEPAIRS];              // tile b -> (ti<<8 | tj)
__device__ double   g_sums[NSLOTS];
__device__ unsigned g_count;
// Sort pipeline state — module-load zeroed; K2's last block re-zeros it each
// replay, so every graph replay sees a clean state.
__device__ int      g_hist[NT];
__device__ int      g_cursor[NT];
__device__ unsigned g_flag;
__device__ unsigned g_k2done;

// K1: LUT build + tile decode table + accumulator zeroing + parallel histogram.
__global__ void prep1_kernel(const float* __restrict__ pot,
                             const int* __restrict__ type_indices) {
    int tid = threadIdx.x;
    int idx = blockIdx.x * 512 + tid;

    if (blockIdx.x == 0 && tid <= NSLOTS) {
        if (tid < NSLOTS) g_sums[tid] = 0.0;
        else g_count = 0u;
    }
    if (idx < LUT_SIZE) {
        int t12 = idx / BINS2;
        int d   = idx - t12 * BINS2;
        float2 v;
        if (d >= BINS) {
            v = make_float2(0.0f, 0.0f);          // pad bin
        } else {
            float e0 = pot[t12 * BINS + d];
            float e1 = (d == BINS - 1) ? e0 : pot[t12 * BINS + d + 1];
            float B  = e1 - e0;
            v = make_float2(fmaf(-(float)d, B, e0), B);
        }
        g_lut[idx] = v;
    }
    if (idx < NTILEPAIRS) {                       // tile decode table
        int b = idx, ti = 0, acc = 0;
        while (acc + (T_TILES - ti) <= b) { acc += T_TILES - ti; ++ti; }
        g_tij[b] = (ti << 8) | (ti + (b - acc));
    }
    // Histogram: first 16 blocks cover all atoms (g_hist starts zeroed;
    // K2's last block re-zeroes it after use).
    if (blockIdx.x < HIST_BLOCKS) {
        __shared__ int sh[NT];
        for (int t = tid; t < NT; t += 512) sh[t] = 0;
        __syncthreads();
        atomicAdd(&sh[type_indices[blockIdx.x * 512 + tid]], 1);
        __syncthreads();
        for (int t = tid; t < NT; t += 512)
            if (sh[t]) atomicAdd(&g_hist[t], sh[t]);
    }
}

// K2: scan (block 0) -> spin -> scatter (1 thread per atom) -> self-clean.
__global__ void prep2_kernel(const float* __restrict__ coords,
                             const int* __restrict__ res_ids,
                             const int* __restrict__ type_indices) {
    int tid = threadIdx.x;

    if (blockIdx.x == 0 && tid == 0) {
        int run = 0;
        for (int t = 0; t < NT; ++t) { g_cursor[t] = run; run += g_hist[t]; }
        __threadfence();
        atomicExch(&g_flag, 1u);
    }
    if (tid == 0) {                               // one spinner per block
        while (atomicAdd(&g_flag, 0u) == 0u) __nanosleep(64);
    }
    __syncthreads();

    int i = blockIdx.x * 512 + tid;               // exactly one atom per thread
    int t = type_indices[i];
    int pos = atomicAdd(&g_cursor[t], 1);
    float x = coords[3 * i + 0] * INV07;
    float y = coords[3 * i + 1] * INV07;
    float z = coords[3 * i + 2] * INV07;
    int   w = (res_ids[i] << 18) | (t * ROWSZ2);
    g_atoms[pos] = make_float4(x, y, z, __int_as_float(w));
    // pair-packed mirror: pair p = pos>>1, slot = pos&1
    float* f = (float*)g_ipairs;
    int p = pos >> 1, s = pos & 1;
    f[8 * p + 0 + s] = x;
    f[8 * p + 2 + s] = y;
    f[8 * p + 4 + s] = z;
    f[8 * p + 6 + s] = __int_as_float(w);

    __syncthreads();
    if (tid == 0) {                               // last block cleans state
        unsigned done = atomicAdd(&g_k2done, 1u);
        if (done == HIST_BLOCKS - 1) {
            for (int t2 = 0; t2 < NT; ++t2) g_hist[t2] = 0;
            g_flag = 0u;
            g_k2done = 0u;
        }
    }
}

// 32 i atoms (16 packed pairs) vs this thread's j atom.
template <bool DIAG>
__device__ __forceinline__ float chunk_sum(const double2* __restrict__ ib,
                                           u64 jxn, u64 jyn, u64 jzn,
                                           int loB, const float2* __restrict__ jlut,
                                           int lim) {
    float acc0 = 0.0f, acc1 = 0.0f;
#pragma unroll
    for (int k = 0; k < 16; ++k) {
        double2 v0 = __ldg(&ib[2 * k + 0]);       // (x0x1, y0y1) uniform LDG.128
        double2 v1 = __ldg(&ib[2 * k + 1]);       // (z0z1, w0w1)
        u64 xs = __double_as_longlong(v0.x);
        u64 ys = __double_as_longlong(v0.y);
        u64 zs = __double_as_longlong(v1.x);
        u64 ws = __double_as_longlong(v1.y);

        u64 dx2, dy2, dz2, d2p;
        F32X2_ADD(dx2, xs, jxn);                  // (xi - xj) x2
        F32X2_ADD(dy2, ys, jyn);
        F32X2_ADD(dz2, zs, jzn);
        F32X2_MUL(d2p, dx2, dx2);
        F32X2_FMA(d2p, dy2, dy2, d2p);
        F32X2_FMA(d2p, dz2, dz2, d2p);            // (d/0.7)^2 for both pairs

        {   // pair 0 (i local = 2k); self-pair NaN routes to pad bin, masked out
            float d2 = lo_f(d2p);
            int   pi = lo_i(ws);
            float ds = d2 * rsqrtf(d2);
            float dsc = fminf(ds, 28.0f);         // NaN -> 28 -> (0,0) pad
            int   d0 = (int)dsc;
            float2 e = __ldg(&jlut[(pi & 0x3FFFF) + d0]);
            bool ok = (unsigned)(pi - loB) >= (5u << 18);   // sep > 2
            if (DIAG) ok &= (2 * k < lim);
            float val = fmaf(e.y, ds, e.x);
            if (ok) acc0 += val;
        }
        {   // pair 1 (i local = 2k+1)
            float d2 = hi_f(d2p);
            int   pi = hi_i(ws);
            float ds = d2 * rsqrtf(d2);
            float dsc = fminf(ds, 28.0f);
            int   d0 = (int)dsc;
            float2 e = __ldg(&jlut[(pi & 0x3FFFF) + d0]);
            bool ok = (unsigned)(pi - loB) >= (5u << 18);
            if (DIAG) ok &= (2 * k + 1 < lim);
            float val = fmaf(e.y, ds, e.x);
            if (ok) acc1 += val;
        }
    }
    return acc0 + acc1;
}

__global__ __launch_bounds__(THREADS, BLOCKS_PER_SM)
void dfire_kernel(float* __restrict__ out) {
    __shared__ double s_warp[THREADS / 32];
    const int tid = threadIdx.x;

    float acc = 0.0f;

    for (int u = blockIdx.x; u < NUNITS; u += GRID_PERSIST) {
        int b  = u >> 2;
        int q  = u & 3;
        int tt = g_tij[b];
        int ti = tt >> 8;
        int tj = tt & 255;

        const double2* ib = g_ipairs + (ti * TILE + q * 32);
        float4 aj = g_atoms[tj * TILE + tid];     // coalesced LDG.128

        int pj    = __float_as_int(aj.w);
        int jres  = pj >> 18;
        int jtype = (pj & 0x3FFFF) / ROWSZ2;
        int loB   = (jres - 2) << 18;
        const float2* jlut = g_lut + jtype * BINS2;
        u64 jxn = pack2(-aj.x, -aj.x);
        u64 jyn = pack2(-aj.y, -aj.y);
        u64 jzn = pack2(-aj.z, -aj.z);

        if (ti == tj) {
            int lim = tid - q * 32;               // i_local < j_local
            acc += chunk_sum<true >(ib, jxn, jyn, jzn, loB, jlut, lim);
        } else {
            acc += chunk_sum<false>(ib, jxn, jyn, jzn, loB, jlut, 0);
        }
    }

#pragma unroll
    for (int off = 16; off > 0; off >>= 1)
        acc += __shfl_xor_sync(0xFFFFFFFFu, acc, off);
    if ((tid & 31) == 0) s_warp[tid >> 5] = (double)acc;
    __syncthreads();

    if (tid == 0) {
        double s = s_warp[0] + s_warp[1] + s_warp[2] + s_warp[3];
        atomicAdd(&g_sums[blockIdx.x & (NSLOTS - 1)], s);
        __threadfence();
        unsigned done = atomicAdd(&g_count, 1u);
        if (done == GRID_PERSIST - 1) {           // last block finalizes
            double tot = 0.0;
#pragma unroll
            for (int k = 0; k < NSLOTS; ++k)
                tot += atomicAdd(&g_sums[k], 0.0);
            out[0] = (float)tot;
        }
    }
}

extern "C" void kernel_launch(void* const* d_in, const int* in_sizes, int n_in,
                              void* d_out, int out_size) {
    // Input order: coords, pot_tensor, res_ids, type_indices, i_idx, j_idx
    const float* coords       = (const float*)d_in[0];
    const float* pot_tensor   = (const float*)d_in[1];
    const int*   res_ids      = (const int*)d_in[2];
    const int*   type_indices = (const int*)d_in[3];
    // i_idx / j_idx are the deterministic triu indices; regenerated implicitly.
    (void)in_sizes; (void)n_in; (void)out_size;
    float* out = (float*)d_out;

    prep1_kernel<<<LUT_BLOCKS, 512>>>(pot_tensor, type_indices);
    prep2_kernel<<<HIST_BLOCKS, 512>>>(coords, res_ids, type_indices);
    dfire_kernel<<<GRID_PERSIST, THREADS>>>(out);
}